// round 3
// baseline (speedup 1.0000x reference)
#include <cuda_runtime.h>

#define ROWS  144
#define NCOLS 576
#define DEG   6
#define ITER  3
#define TPB   192

// Sparse structure of H, built on-device each call (deterministic, tiny).
__device__ int g_cols[ROWS * DEG];   // column indices of the 6 ones per row
__device__ int g_coldeg[NCOLS];      // number of rows covering each column

__global__ void prep_kernel(const float* __restrict__ H) {
    int t = threadIdx.x;
    if (t < ROWS) {
        int c = 0;
        int base = t * NCOLS;
        for (int j = 0; j < NCOLS; ++j) {
            if (H[base + j] != 0.0f) {
                if (c < DEG) g_cols[t * DEG + c] = j;
                ++c;
            }
        }
    }
    if (t < NCOLS) {
        int d = 0;
        for (int i = 0; i < ROWS; ++i)
            if (H[i * NCOLS + t] != 0.0f) ++d;
        g_coldeg[t] = d;
    }
}

// Soft quantization: softmax over squared distance to the 4 levels.
__device__ __forceinline__ float quantize4(float x, float inv2e,
                                           float q0, float q1, float q2, float q3)
{
    float d0 = x - q0, d1 = x - q1, d2 = x - q2, d3 = x - q3;
    float l0 = -d0 * d0 * inv2e;
    float l1 = -d1 * d1 * inv2e;
    float l2 = -d2 * d2 * inv2e;
    float l3 = -d3 * d3 * inv2e;
    float m  = fmaxf(fmaxf(l0, l1), fmaxf(l2, l3));
    float w0 = __expf(l0 - m);
    float w1 = __expf(l1 - m);
    float w2 = __expf(l2 - m);
    float w3 = __expf(l3 - m);
    float den = (w0 + w1) + (w2 + w3);
    float num = w0 * q0 + w1 * q1 + w2 * q2 + w3 * q3;
    return __fdividef(num, den);
}

__device__ __forceinline__ float signf0(float x) {
    // jnp.sign semantics: sign(0) == 0
    return (x > 0.0f) ? 1.0f : ((x < 0.0f) ? -1.0f : 0.0f);
}

__global__ __launch_bounds__(TPB) void decode_kernel(
    const float* __restrict__ r,
    const float* __restrict__ alpha,
    const float* __restrict__ beta,
    const float* __restrict__ eta,
    const float* __restrict__ qk,
    float* __restrict__ out)
{
    __shared__ float sr[NCOLS];    // r for this batch element
    __shared__ float scol[NCOLS];  // per-column sum of E (incl. off-support correction)

    const int tid = threadIdx.x;
    const int b   = blockIdx.x;
    const float* rb = r + (size_t)b * NCOLS;

    const float q0 = qk[0], q1 = qk[1], q2 = qk[2], q3 = qk[3];

    #pragma unroll
    for (int j = tid; j < NCOLS; j += TPB) sr[j] = rb[j];

    int   ci[DEG];
    float M[DEG], E[DEG], S[DEG];
    if (tid < ROWS) {
        #pragma unroll
        for (int k = 0; k < DEG; ++k) ci[k] = g_cols[tid * DEG + k];
    }
    __syncthreads();
    if (tid < ROWS) {
        #pragma unroll
        for (int k = 0; k < DEG; ++k) M[k] = sr[ci[k]];  // M = H * r at support
    }

    for (int t = 0; t < ITER; ++t) {
        const float a     = alpha[t];
        const float bt    = beta[t];
        const float et    = eta[t];
        const float inv2e = 1.0f / (2.0f * et * et + 1e-12f);
        // quantize(0): off-support entries of E quantize to this tiny value and
        // DO enter sum_E in the reference (144 - coldeg of them per column).
        const float qz0 = quantize4(0.0f, inv2e, q0, q1, q2, q3);

        __syncthreads();  // previous iteration's readers of scol are done
        #pragma unroll
        for (int j = tid; j < NCOLS; j += TPB)
            scol[j] = (float)(ROWS - g_coldeg[j]) * qz0;

        if (tid < ROWS) {
            // Row stats: two smallest |M|, argmin, product of signs.
            float min1 = 3.0e38f, min2 = 3.0e38f, sp = 1.0f;
            int idx = 0;
            #pragma unroll
            for (int k = 0; k < DEG; ++k) {
                float am = fabsf(M[k]);
                S[k] = signf0(M[k]);
                sp *= S[k];
                if (am < min1) { min2 = min1; min1 = am; idx = k; }
                else if (am < min2) { min2 = am; }
            }
            #pragma unroll
            for (int k = 0; k < DEG; ++k) {
                float eab = (k == idx) ? min2 : min1;
                float e   = a * sp * S[k] * fmaxf(0.0f, eab - bt);
                E[k] = quantize4(e, inv2e, q0, q1, q2, q3);
            }
        }
        __syncthreads();  // scol init complete
        if (tid < ROWS) {
            #pragma unroll
            for (int k = 0; k < DEG; ++k) atomicAdd(&scol[ci[k]], E[k]);
        }
        __syncthreads();  // column sums complete
        if (t + 1 < ITER && tid < ROWS) {
            // Extrinsic update + quantize (dead on the last iteration).
            #pragma unroll
            for (int k = 0; k < DEG; ++k)
                M[k] = quantize4(sr[ci[k]] + scol[ci[k]] - E[k], inv2e,
                                 q0, q1, q2, q3);
        }
    }

    #pragma unroll
    for (int j = tid; j < NCOLS; j += TPB)
        out[(size_t)b * NCOLS + j] = sr[j] + scol[j];
}

extern "C" void kernel_launch(void* const* d_in, const int* in_sizes, int n_in,
                              void* d_out, int out_size)
{
    const float* r     = (const float*)d_in[0];
    const float* H     = (const float*)d_in[1];
    const float* alpha = (const float*)d_in[2];
    const float* beta  = (const float*)d_in[3];
    const float* eta   = (const float*)d_in[4];
    const float* qk    = (const float*)d_in[5];
    float* out = (float*)d_out;

    const int batch = in_sizes[0] / NCOLS;  // 512

    prep_kernel<<<1, NCOLS>>>(H);
    decode_kernel<<<batch, TPB>>>(r, alpha, beta, eta, qk, out);
}

// round 4
// speedup vs baseline: 3.8826x; 3.8826x over previous
#include <cuda_runtime.h>

#define ROWS  144
#define NCOLS 576
#define DEG   6
#define ITER  3
#define TPB   288   // 2 batches x 144 rows
#define BPB   2

// Sparse structure of H: column indices of the 6 ones per row.
__device__ int g_cols[ROWS * DEG];

// One block per row, 576 threads: coalesced read + ballot-based ordered rank.
__global__ void prep_kernel(const float* __restrict__ H) {
    __shared__ int wcnt[18];
    __shared__ int wpre[18];
    const int row  = blockIdx.x;
    const int j    = threadIdx.x;          // 0..575
    const int w    = j >> 5, lane = j & 31;
    const float v  = H[row * NCOLS + j];
    const unsigned mask = __ballot_sync(0xffffffffu, v != 0.0f);
    if (lane == 0) wcnt[w] = __popc(mask);
    __syncthreads();
    if (j == 0) {
        int s = 0;
        #pragma unroll
        for (int k = 0; k < 18; ++k) { wpre[k] = s; s += wcnt[k]; }
    }
    __syncthreads();
    if (v != 0.0f) {
        int rank = wpre[w] + __popc(mask & ((1u << lane) - 1u));
        if (rank < DEG) g_cols[row * DEG + rank] = j;
    }
}

__global__ __launch_bounds__(TPB) void decode_kernel(
    const float* __restrict__ r,
    const float* __restrict__ alpha,
    const float* __restrict__ beta,
    const float* __restrict__ eta,
    const float* __restrict__ qk,
    float* __restrict__ out,
    int batch)
{
    __shared__ float sr[BPB * NCOLS];        // r for the block's batch elements
    __shared__ float sc[2][BPB * NCOLS];     // double-buffered column sums

    const int tid = threadIdx.x;
    const int b0  = blockIdx.x * BPB;
    const int nb  = (batch - b0 < BPB) ? (batch - b0) : BPB;
    const int NJ  = nb * NCOLS;

    const float q0 = qk[0], q1 = qk[1], q2 = qk[2], q3 = qk[3];

    for (int j = tid; j < NJ; j += TPB)
        sr[j] = r[(size_t)b0 * NCOLS + j];

    const int  lb     = tid / ROWS;          // local batch element: 0 or 1
    const int  row    = tid - lb * ROWS;
    const bool active = (lb < nb);
    const int  base   = lb * NCOLS;

    int   ci[DEG];
    float M[DEG], E[DEG], S[DEG];
    if (active) {
        #pragma unroll
        for (int k = 0; k < DEG; ++k) ci[k] = g_cols[row * DEG + k] + base;
    }
    __syncthreads();
    if (active) {
        #pragma unroll
        for (int k = 0; k < DEG; ++k) M[k] = sr[ci[k]];   // M = H*r at support
    }

    #pragma unroll
    for (int t = 0; t < ITER; ++t) {
        const float a    = alpha[t];
        const float bt   = beta[t];
        const float et   = eta[t];
        const float c    = 1.0f / (2.0f * et * et + 1e-12f);
        const float twoC = 2.0f * c;
        const float c0 = q0 * q0 * c, c1 = q1 * q1 * c;
        const float c2 = q2 * q2 * c, c3 = q3 * q3 * c;

        // Soft quantization. Softmax is shift-invariant: drop the x^2 term,
        // l_i = c*(2*x*q_i - q_i^2). Max-subtraction keeps it overflow-safe.
        auto quant = [&](float x) -> float {
            float s  = x * twoC;
            float l0 = fmaf(s, q0, -c0);
            float l1 = fmaf(s, q1, -c1);
            float l2 = fmaf(s, q2, -c2);
            float l3 = fmaf(s, q3, -c3);
            float m  = fmaxf(fmaxf(l0, l1), fmaxf(l2, l3));
            float w0 = __expf(l0 - m), w1 = __expf(l1 - m);
            float w2 = __expf(l2 - m), w3 = __expf(l3 - m);
            float den = (w0 + w1) + (w2 + w3);
            float num = fmaf(w0, q0, fmaf(w1, q1, fmaf(w2, q2, w3 * q3)));
            return __fdividef(num, den);
        };

        // quantize(0): off-support E entries still enter sum_E in the reference.
        // sum_E[j] = 144*qz0 + sum_{rows covering j}(E - qz0).
        const float qz0 = quant(0.0f);
        float* cs = sc[t & 1];
        const float init = (float)ROWS * qz0;
        for (int j = tid; j < NJ; j += TPB) cs[j] = init;

        if (active) {
            float min1 = 3.0e38f, min2 = 3.0e38f, sp = 1.0f;
            int idx = 0;
            #pragma unroll
            for (int k = 0; k < DEG; ++k) {
                float m_ = M[k];
                float am = fabsf(m_);
                float sg = (m_ > 0.0f) ? 1.0f : ((m_ < 0.0f) ? -1.0f : 0.0f);
                S[k] = sg;
                sp  *= sg;
                if (am < min1)      { min2 = min1; min1 = am; idx = k; }
                else if (am < min2) { min2 = am; }
            }
            const float asp = a * sp;
            #pragma unroll
            for (int k = 0; k < DEG; ++k) {
                float eab = (k == idx) ? min2 : min1;
                E[k] = quant(asp * S[k] * fmaxf(0.0f, eab - bt));
            }
        }
        __syncthreads();   // cs init visible (and prior-iter readers done)
        if (active) {
            #pragma unroll
            for (int k = 0; k < DEG; ++k) atomicAdd(&cs[ci[k]], E[k] - qz0);
        }
        __syncthreads();   // column sums complete
        if (t + 1 < ITER && active) {
            #pragma unroll
            for (int k = 0; k < DEG; ++k)
                M[k] = quant(sr[ci[k]] + cs[ci[k]] - E[k]);
        }
    }

    const float* csf = sc[(ITER - 1) & 1];
    for (int j = tid; j < NJ; j += TPB)
        out[(size_t)b0 * NCOLS + j] = sr[j] + csf[j];
}

extern "C" void kernel_launch(void* const* d_in, const int* in_sizes, int n_in,
                              void* d_out, int out_size)
{
    const float* r     = (const float*)d_in[0];
    const float* H     = (const float*)d_in[1];
    const float* alpha = (const float*)d_in[2];
    const float* beta  = (const float*)d_in[3];
    const float* eta   = (const float*)d_in[4];
    const float* qk    = (const float*)d_in[5];
    float* out = (float*)d_out;

    const int batch  = in_sizes[0] / NCOLS;          // 512
    const int blocks = (batch + BPB - 1) / BPB;      // 256

    prep_kernel<<<ROWS, NCOLS>>>(H);
    decode_kernel<<<blocks, TPB>>>(r, alpha, beta, eta, qk, out, batch);
}

// round 5
// speedup vs baseline: 5.1378x; 1.3233x over previous
#include <cuda_runtime.h>

#define ROWS  144
#define NCOLS 576
#define DEG   6
#define ITER  3
#define TPB   288   // 2 threads per row, 144 rows, 1 batch element per block

// Sparse structure of H: column indices of the 6 ones per row.
__device__ int   g_cols[ROWS * DEG];
// Per-iteration quantizer constants:
// [0]=lam (=2*c*delta), [1..4]=k_i=exp(-c*q_i^2), [5..8]=k_i*q_i,
// [9]=qz0=quantize(0), [10]=144*qz0
__device__ float g_q[ITER][11];

// One block per row, 576 threads: coalesced read + ballot-based ordered rank.
// Block 0 / thread 0 additionally precomputes the quantizer constants.
__global__ void prep_kernel(const float* __restrict__ H,
                            const float* __restrict__ eta,
                            const float* __restrict__ qk)
{
    __shared__ int wcnt[18];
    __shared__ int wpre[18];
    const int row  = blockIdx.x;
    const int j    = threadIdx.x;          // 0..575
    const int w    = j >> 5, lane = j & 31;
    const float v  = H[row * NCOLS + j];
    const unsigned mask = __ballot_sync(0xffffffffu, v != 0.0f);
    if (lane == 0) wcnt[w] = __popc(mask);
    __syncthreads();
    if (j == 0) {
        int s = 0;
        #pragma unroll
        for (int k = 0; k < 18; ++k) { wpre[k] = s; s += wcnt[k]; }
    }
    __syncthreads();
    if (v != 0.0f) {
        int rank = wpre[w] + __popc(mask & ((1u << lane) - 1u));
        if (rank < DEG) g_cols[row * DEG + rank] = j;
    }

    if (row == 0 && j == 0) {
        const float q0 = qk[0], q1 = qk[1], q2 = qk[2], q3 = qk[3];
        const float dq = (q3 - q0) * (1.0f / 3.0f);
        #pragma unroll
        for (int t = 0; t < ITER; ++t) {
            float et  = eta[t];
            float c   = 1.0f / (2.0f * et * et + 1e-12f);
            float lam = 2.0f * c * dq;
            float k0 = __expf(-c * q0 * q0), k1 = __expf(-c * q1 * q1);
            float k2 = __expf(-c * q2 * q2), k3 = __expf(-c * q3 * q3);
            g_q[t][0] = lam;
            g_q[t][1] = k0; g_q[t][2] = k1; g_q[t][3] = k2; g_q[t][4] = k3;
            g_q[t][5] = k0 * q0; g_q[t][6] = k1 * q1;
            g_q[t][7] = k2 * q2; g_q[t][8] = k3 * q3;
            // quantize(0): v=1 -> all weights = k_i
            float den = (k0 + k1) + (k2 + k3);
            float num = (k0 * q0 + k1 * q1) + (k2 * q2 + k3 * q3);
            float qz0 = num / den;
            g_q[t][9]  = qz0;
            g_q[t][10] = (float)ROWS * qz0;
        }
    }
}

__global__ __launch_bounds__(TPB) void decode_kernel(
    const float* __restrict__ r,
    const float* __restrict__ alpha,
    const float* __restrict__ beta,
    float* __restrict__ out)
{
    __shared__ float sr[NCOLS];         // r for this batch element
    __shared__ float sc[2][NCOLS];      // double-buffered column sums

    const int tid  = threadIdx.x;
    const int b    = blockIdx.x;
    const int row  = tid >> 1;          // 0..143
    const int half = tid & 1;           // which 3 edges of the row

    // Vectorized load of r (288 float2 = 576 floats)
    ((float2*)sr)[tid] = ((const float2*)(r + (size_t)b * NCOLS))[tid];

    int   ci[3];
    float M[3], E[3], S[3];
    #pragma unroll
    for (int k = 0; k < 3; ++k) ci[k] = g_cols[row * DEG + half * 3 + k];
    __syncthreads();
    #pragma unroll
    for (int k = 0; k < 3; ++k) M[k] = sr[ci[k]];   // M = H*r at support

    #pragma unroll
    for (int t = 0; t < ITER; ++t) {
        const float lam = g_q[t][0];
        const float k0 = g_q[t][1], k1 = g_q[t][2];
        const float k2 = g_q[t][3], k3 = g_q[t][4];
        const float kq0 = g_q[t][5], kq1 = g_q[t][6];
        const float kq2 = g_q[t][7], kq3 = g_q[t][8];
        const float qz0  = g_q[t][9];
        const float init = g_q[t][10];
        const float a  = alpha[t];
        const float bt = beta[t];

        // Soft quantization via geometric weights:
        //   w_i ∝ k_i * u^i, u = exp(2*c*dq*x). Overflow-safe: factor out the
        //   largest power (sign-dependent), using v = exp(-lam*|x|) <= 1.
        auto quant = [&](float x) -> float {
            float v  = __expf(-lam * fabsf(x));
            float v2 = v * v;
            float v3 = v2 * v;
            bool  p  = (x >= 0.0f);
            float a0 = p ? v3 : 1.0f;
            float a1 = p ? v2 : v;
            float a2 = p ? v  : v2;
            float a3 = p ? 1.0f : v3;
            float den = fmaf(a0, k0,  fmaf(a1, k1,  fmaf(a2, k2,  a3 * k3)));
            float num = fmaf(a0, kq0, fmaf(a1, kq1, fmaf(a2, kq2, a3 * kq3)));
            return __fdividef(num, den);
        };

        // Init column sums: sum_E[j] = 144*qz0 + sum_{support}(E - qz0)
        float* cs = sc[t & 1];
        ((float2*)cs)[tid] = make_float2(init, init);

        // Row stats over this thread's 3 edges
        float m1 = 3.0e38f, m2 = 3.0e38f, sp = 1.0f;
        int   id = 0;
        #pragma unroll
        for (int k = 0; k < 3; ++k) {
            float m_ = M[k];
            float am = fabsf(m_);
            float sg = (m_ > 0.0f) ? 1.0f : ((m_ < 0.0f) ? -1.0f : 0.0f);
            S[k] = sg;
            sp  *= sg;
            int gk = half * 3 + k;
            if (am < m1)      { m2 = m1; m1 = am; id = gk; }
            else if (am < m2) { m2 = am; }
        }
        // Merge with partner half (pairs are intra-warp: lanes 2u, 2u+1)
        float om1 = __shfl_xor_sync(0xffffffffu, m1, 1);
        float om2 = __shfl_xor_sync(0xffffffffu, m2, 1);
        int   oid = __shfl_xor_sync(0xffffffffu, id, 1);
        float osp = __shfl_xor_sync(0xffffffffu, sp, 1);
        sp *= osp;
        if (om1 < m1 || (om1 == m1 && oid < id)) {
            m2 = fminf(m1, om2); m1 = om1; id = oid;
        } else {
            m2 = fminf(m2, om1);
        }

        const float asp = a * sp;
        #pragma unroll
        for (int k = 0; k < 3; ++k) {
            int gk = half * 3 + k;
            float eab = (gk == id) ? m2 : m1;
            E[k] = quant(asp * S[k] * fmaxf(0.0f, eab - bt));
        }
        __syncthreads();   // cs init visible; prior-iter M updates done
        #pragma unroll
        for (int k = 0; k < 3; ++k) atomicAdd(&cs[ci[k]], E[k] - qz0);
        __syncthreads();   // column sums complete
        if (t + 1 < ITER) {
            #pragma unroll
            for (int k = 0; k < 3; ++k)
                M[k] = quant(sr[ci[k]] + cs[ci[k]] - E[k]);
        }
    }

    const float* csf = sc[(ITER - 1) & 1];
    float2 sv = ((const float2*)sr)[tid];
    float2 cv = ((const float2*)csf)[tid];
    ((float2*)(out + (size_t)b * NCOLS))[tid] =
        make_float2(sv.x + cv.x, sv.y + cv.y);
}

extern "C" void kernel_launch(void* const* d_in, const int* in_sizes, int n_in,
                              void* d_out, int out_size)
{
    const float* r     = (const float*)d_in[0];
    const float* H     = (const float*)d_in[1];
    const float* alpha = (const float*)d_in[2];
    const float* beta  = (const float*)d_in[3];
    const float* eta   = (const float*)d_in[4];
    const float* qk    = (const float*)d_in[5];
    float* out = (float*)d_out;

    const int batch = in_sizes[0] / NCOLS;   // 512

    prep_kernel<<<ROWS, NCOLS>>>(H, eta, qk);
    decode_kernel<<<batch, TPB>>>(r, alpha, beta, out);
}